// round 1
// baseline (speedup 1.0000x reference)
#include <cuda_runtime.h>
#include <cstdint>

// one_hot: label (4096x4096 int32) -> out (8, 4096, 4096) float32
// out[n, h, w] = (label[h, w] == n) ? 1.0f : 0.0f
//
// Pure HBM streaming: 64 MiB read + 512 MiB write. Strategy:
//   - int4 (16B) label loads, read-once (__ldcs)
//   - float4 (16B) stores per plane, streaming (__stcs) to avoid L2 churn
//   - fully coalesced: thread i handles labels [4i, 4i+4); plane stride H*W.

#define H 4096
#define W 4096
#define NCLS 8
#define HW (H * W)          // 16777216
#define NVEC (HW / 4)       // 4194304 float4/int4 vectors per plane

__global__ void __launch_bounds__(256) onehot_kernel(
    const int4* __restrict__ lab4, float4* __restrict__ out4)
{
    unsigned i = blockIdx.x * 256u + threadIdx.x;   // 0 .. NVEC-1
    int4 l = __ldcs(lab4 + i);

#pragma unroll
    for (int n = 0; n < NCLS; n++) {
        float4 v;
        v.x = (l.x == n) ? 1.0f : 0.0f;
        v.y = (l.y == n) ? 1.0f : 0.0f;
        v.z = (l.z == n) ? 1.0f : 0.0f;
        v.w = (l.w == n) ? 1.0f : 0.0f;
        __stcs(out4 + (size_t)n * NVEC + i, v);
    }
}

extern "C" void kernel_launch(void* const* d_in, const int* in_sizes, int n_in,
                              void* d_out, int out_size)
{
    const int4* lab4 = (const int4*)d_in[0];
    float4* out4 = (float4*)d_out;
    // NVEC threads total, 256 per block -> 16384 blocks
    onehot_kernel<<<NVEC / 256, 256>>>(lab4, out4);
}